// round 7
// baseline (speedup 1.0000x reference)
#include <cuda_runtime.h>
#include <cstdint>
#include <cstddef>

#define BATCH   32
#define PRIORS  32768
#define NUMC    21
#define NCLS    20
#define NMSK    1000
#define TOPK    200
#define CONF_T  0.01f
#define NMS_T   0.3f
#define NT      256
#define T0F     0.95f
#define CAP     2048
#define SPLIT   8

typedef unsigned long long ull;
#define FULL 0xffffffffu

__device__ float  g_conf_t[(size_t)BATCH * NCLS * PRIORS];   // [b][c][p]
__device__ float4 g_decoded[(size_t)BATCH * PRIORS];
__device__ ull    g_cand[(size_t)BATCH * NCLS * CAP];
__device__ int    g_cnt[BATCH * NCLS];
__device__ int    g_cntlow[BATCH * NCLS];

// ---------------------------------------------------------------------------
// Kernel 1: decode boxes + transpose conf + zero counters
// ---------------------------------------------------------------------------
__global__ void prep_kernel(const float* __restrict__ loc,
                            const float* __restrict__ conf,
                            const float* __restrict__ prior) {
    int idx = blockIdx.x * blockDim.x + threadIdx.x;
    if (idx < BATCH * NCLS) { g_cnt[idx] = 0; g_cntlow[idx] = 0; }
    if (idx >= BATCH * PRIORS) return;
    int b = idx >> 15;
    int p = idx & (PRIORS - 1);

    float4 l  = reinterpret_cast<const float4*>(loc)[idx];
    float4 pr = reinterpret_cast<const float4*>(prior)[p];

    float cx = pr.x + (l.x * 0.1f) * pr.z;
    float cy = pr.y + (l.y * 0.1f) * pr.w;
    float w  = pr.z * expf(l.z * 0.2f);
    float h  = pr.w * expf(l.w * 0.2f);
    float x1 = cx - w * 0.5f;
    float y1 = cy - h * 0.5f;
    g_decoded[idx] = make_float4(x1, y1, x1 + w, y1 + h);

    const float* crow = conf + (size_t)idx * NUMC;
    size_t base = ((size_t)b * NCLS) << 15;
#pragma unroll
    for (int c = 0; c < NCLS; ++c)
        g_conf_t[base + ((size_t)c << 15) + p] = crow[c + 1];
}

// ---------------------------------------------------------------------------
// Kernel 2: wide-grid candidate gather from class-major conf
// grid = BATCH*NCLS*SPLIT blocks; each block scans a contiguous 4096-elem slice
// ---------------------------------------------------------------------------
__global__ __launch_bounds__(NT) void gather_kernel() {
    int gb  = blockIdx.x;
    int bc  = gb >> 3;                 // SPLIT = 8
    int sl  = gb & 7;
    int tid = threadIdx.x;
    int lane = tid & 31;

    const float4* sc4 = reinterpret_cast<const float4*>(g_conf_t + ((size_t)bc << 15))
                        + sl * (PRIORS / 4 / SPLIT);
    ull* cand = g_cand + (size_t)bc * CAP;
    unsigned int pbase = (unsigned int)(sl * (PRIORS / SPLIT));

    int lowc = 0;
#pragma unroll
    for (int it = 0; it < PRIORS / 4 / SPLIT / NT; ++it) {   // 4 iterations
        int i = it * NT + tid;
        float4 v = sc4[i];
        float vv[4] = {v.x, v.y, v.z, v.w};
#pragma unroll
        for (int c = 0; c < 4; ++c) {
            float x = vv[c];
            bool pass = (x > T0F);
            lowc += (x > CONF_T && !pass);
            unsigned int pm = __ballot_sync(FULL, pass);
            if (pm) {
                int leader = __ffs(pm) - 1;
                int n = __popc(pm);
                int base;
                if (lane == leader) base = atomicAdd(&g_cnt[bc], n);
                base = __shfl_sync(FULL, base, leader);
                if (pass) {
                    int pos = base + __popc(pm & ((1u << lane) - 1u));
                    if (pos < CAP) {
                        unsigned int p = pbase + (unsigned int)(i * 4 + c);
                        cand[pos] = ((ull)__float_as_uint(x) << 32)
                                  | (ull)(0xFFFFFFFFu - p);
                    }
                }
            }
        }
    }
#pragma unroll
    for (int o = 16; o; o >>= 1) lowc += __shfl_down_sync(FULL, lowc, o);
    if (lane == 0 && lowc) atomicAdd(&g_cntlow[bc], lowc);
}

// ---------------------------------------------------------------------------
// Kernel 3: per (batch,class) select top-1000 + serial greedy NMS + output
// ---------------------------------------------------------------------------
__global__ __launch_bounds__(NT) void nms_kernel(float* __restrict__ out) {
    const int bx = blockIdx.x, b = bx / NUMC, cc = bx % NUMC;
    const int tid = threadIdx.x;
    float* outp = out + (size_t)bx * (TOPK * 5);

    if (cc == 0) {
        for (int i = tid; i < TOPK * 5; i += NT) outp[i] = 0.f;
        return;
    }
    const int bc = b * NCLS + (cc - 1);

    __shared__ __align__(16) unsigned char s_mem[28672];
    ull*    s_keys = reinterpret_cast<ull*>(s_mem);            // [0,16K)
    ull*    s_dst  = reinterpret_cast<ull*>(s_mem + 16384);    // [16K,24K)
    int*    s_hist = reinterpret_cast<int*>(s_mem);            // fallback
    float4* s_box  = reinterpret_cast<float4*>(s_mem);         // [0,16K) late
    float*  s_val  = reinterpret_cast<float*>(s_mem + 24576);  // [24K,28K)
    __shared__ int s_shist[256];
    __shared__ unsigned int s_sup[32];
    __shared__ int s_keep[TOPK];
    __shared__ int s_cnt2, s_pivch, s_pivkk, s_pivbin, s_selb, s_sab, s_pc;
    __shared__ unsigned int s_umax;

    const int lane = tid & 31;
    const int wid  = tid >> 5;

    int cnt = g_cnt[bc];
    bool need_fb = (cnt > CAP) || (cnt < NMSK && g_cntlow[bc] > 0);
    unsigned int Tgt = __float_as_uint(T0F);

    if (tid == 0) s_umax = 0u;
    __syncthreads();

    if (!need_fb) {
        const ull* cand = g_cand + (size_t)bc * CAP;
        unsigned int um = 0u;
        for (int i = tid; i < cnt; i += NT) {
            ull k = __ldg(cand + i);
            s_keys[i] = k;
            unsigned int bits = (unsigned int)(k >> 32);
            um = um > bits ? um : bits;
        }
#pragma unroll
        for (int o = 16; o; o >>= 1) {
            unsigned int t = __shfl_down_sync(FULL, um, o);
            um = um > t ? um : t;
        }
        if (lane == 0) atomicMax(&s_umax, um);
        __syncthreads();
    } else {
        // ------ exact fallback: 12-bit histogram over contiguous conf_t row ------
        const float4* sc4 = reinterpret_cast<const float4*>(g_conf_t + ((size_t)bc << 15));
        for (int i = tid; i < 4096; i += NT) s_hist[i] = 0;
        if (tid == 0) s_pivch = -1;
        __syncthreads();
        for (int i = tid; i < PRIORS / 4; i += NT) {
            float4 v = sc4[i];
            float vv[4] = {v.x, v.y, v.z, v.w};
#pragma unroll
            for (int c = 0; c < 4; ++c) {
                unsigned int bits = (vv[c] > CONF_T) ? __float_as_uint(vv[c]) : 0u;
                atomicAdd(&s_hist[bits >> 20], 1);
            }
        }
        __syncthreads();
        { int cs = 0; for (int j = 0; j < 16; ++j) cs += s_hist[tid * 16 + j]; s_shist[tid] = cs; }
        __syncthreads();
        for (int d = 1; d < 256; d <<= 1) {
            int v = (tid + d < 256) ? s_shist[tid + d] : 0;
            __syncthreads();
            s_shist[tid] += v;
            __syncthreads();
        }
        { int suf = s_shist[tid]; int sufn = (tid < 255) ? s_shist[tid + 1] : 0;
          if (suf >= NMSK && sufn < NMSK) { s_pivch = tid; s_pivkk = NMSK - sufn; } }
        __syncthreads();
        if (tid == 0) {
            int pb = 1;
            if (s_pivch >= 0) {
                int ch = s_pivch, kk = s_pivkk, run = 0;
                for (int j = 15; j >= 0; --j) {
                    run += s_hist[ch * 16 + j];
                    if (run >= kk) { pb = ch * 16 + j; break; }
                }
            }
            if (pb < 1) pb = 1;
            s_pivbin = pb; s_cnt2 = 0; s_umax = 0u;
        }
        __syncthreads();
        Tgt = (((unsigned int)s_pivbin) << 20) - 1u;
        unsigned int um = 0u;
        for (int i = tid; i < PRIORS / 4; i += NT) {
            float4 v = sc4[i];
            float vv[4] = {v.x, v.y, v.z, v.w};
#pragma unroll
            for (int c = 0; c < 4; ++c) {
                float x = vv[c];
                unsigned int bits = __float_as_uint(x);
                if (x > CONF_T && bits > Tgt) {
                    int pos = atomicAdd(&s_cnt2, 1);
                    if (pos < CAP)
                        s_keys[pos] = ((ull)bits << 32)
                                    | (ull)(0xFFFFFFFFu - (unsigned int)(i * 4 + c));
                    um = um > bits ? um : bits;
                }
            }
        }
#pragma unroll
        for (int o = 16; o; o >>= 1) {
            unsigned int t = __shfl_down_sync(FULL, um, o);
            um = um > t ? um : t;
        }
        if (lane == 0) atomicMax(&s_umax, um);
        __syncthreads();
        cnt = s_cnt2; if (cnt > CAP - 1) cnt = CAP - 1;
    }

    // ---------- refine to <=1024 ----------
    bool sorted2048 = false;
    int sabove = cnt;
    if (cnt > 1024) {
        unsigned int base = Tgt;
        unsigned int span = s_umax - base;
        int nbits = 32 - __clz((int)span);
        int shift = nbits > 8 ? nbits - 8 : 0;
        s_shist[tid] = 0;
        if (tid == 0) s_selb = -1;
        __syncthreads();
        for (int i = tid; i < cnt; i += NT) {
            unsigned int bits = (unsigned int)(s_keys[i] >> 32);
            atomicAdd(&s_shist[(bits - base) >> shift], 1);
        }
        __syncthreads();
        if (wid == 0) {
            int base8 = lane * 8;
            int h[8]; int s = 0;
#pragma unroll
            for (int j = 0; j < 8; ++j) { h[j] = s_shist[base8 + j]; s += h[j]; }
            int suf = s;
#pragma unroll
            for (int o = 1; o < 32; o <<= 1) {
                int t = __shfl_down_sync(FULL, suf, o);
                if (lane + o < 32) suf += t;
            }
            int sufn = __shfl_down_sync(FULL, suf, 1);
            if (lane == 31) sufn = 0;
            if (suf >= NMSK && sufn < NMSK) {
                int run = 0;
#pragma unroll
                for (int j = 7; j >= 0; --j) {
                    run += h[j];
                    if (sufn + run >= NMSK) { s_selb = base8 + j; s_sab = sufn + run; break; }
                }
            }
        }
        __syncthreads();
        int selb = s_selb;
        if (selb >= 0 && s_sab <= 1024) {
            unsigned int T2 = base + (((unsigned int)selb) << shift);
            if (tid == 0) s_pc = 0;
            for (int i = tid; i < 1024; i += NT) s_dst[i] = 0ull;
            __syncthreads();
            for (int i = tid; i < cnt; i += NT) {
                ull k = s_keys[i];
                if ((unsigned int)(k >> 32) >= T2) {
                    int p = atomicAdd(&s_pc, 1);
                    if (p < 1024) s_dst[p] = k;
                }
            }
            sabove = s_sab;
        } else {
            for (int i = cnt + tid; i < 2048; i += NT) s_keys[i] = 0ull;
            for (int k2 = 2; k2 <= 2048; k2 <<= 1) {
                for (int j = k2 >> 1; j > 0; j >>= 1) {
                    __syncthreads();
                    for (int i = tid; i < 2048; i += NT) {
                        int l = i ^ j;
                        if (l > i) {
                            ull a = s_keys[i], bb = s_keys[l];
                            bool up = ((i & k2) == 0);
                            if (up ? (a < bb) : (a > bb)) { s_keys[i] = bb; s_keys[l] = a; }
                        }
                    }
                }
            }
            __syncthreads();
            for (int i = tid; i < 1024; i += NT) s_dst[i] = (i < NMSK) ? s_keys[i] : 0ull;
            sorted2048 = true;
        }
    } else {
        for (int i = tid; i < 1024; i += NT) s_dst[i] = (i < cnt) ? s_keys[i] : 0ull;
    }
    __syncthreads();
    if (!sorted2048) {
        for (int k2 = 2; k2 <= 1024; k2 <<= 1) {
            for (int j = k2 >> 1; j > 0; j >>= 1) {
                if (j >= 16) __syncthreads(); else __syncwarp();
                for (int i = tid; i < 1024; i += NT) {
                    int l = i ^ j;
                    if (l > i) {
                        ull a = s_dst[i], bb = s_dst[l];
                        bool up = ((i & k2) == 0);
                        if (up ? (a < bb) : (a > bb)) { s_dst[i] = bb; s_dst[l] = a; }
                    }
                }
            }
        }
        __syncthreads();
    }

    // ---------- extract boxes (s_box aliases dead s_keys) ----------
    const float4* dec = g_decoded + ((size_t)b << 15);
    const int nvalid = sabove < NMSK ? sabove : NMSK;
    for (int r = tid; r < 1024; r += NT) {
        float v = 0.f;
        float4 bb = make_float4(0.f, 0.f, 0.f, 0.f);
        if (r < NMSK) {
            ull key = s_dst[r];
            unsigned int bits = (unsigned int)(key >> 32);
            v = __uint_as_float(bits);
            if (v > CONF_T) {
                unsigned int p = 0xFFFFFFFFu - (unsigned int)(key & 0xFFFFFFFFull);
                bb = __ldg(dec + p);
            } else v = 0.f;
        }
        s_box[r] = bb;
        s_val[r] = v;
    }
    if (tid < 32) s_sup[tid] = 0u;
    __syncthreads();

    // ---------- serial greedy NMS, one barrier per kept candidate ----------
    int nkeep = 0;
    for (int k = 0; k < nvalid; ++k) {
        float vk = s_val[k];
        if (vk <= CONF_T) break;
        bool sup = (s_sup[k >> 5] >> (k & 31)) & 1u;
        if (!sup) {
            if (tid == 0) s_keep[nkeep] = k;
            nkeep++;
            if (nkeep >= TOPK) break;
            float4 bk = s_box[k];
            float ka = (bk.z - bk.x) * (bk.w - bk.y);
            for (int j = k + 1 + tid; j < nvalid; j += NT) {
                float4 bj = s_box[j];
                float aj = (bj.z - bj.x) * (bj.w - bj.y);
                float w = fminf(bj.z, bk.z) - fmaxf(bj.x, bk.x);
                float h = fminf(bj.w, bk.w) - fmaxf(bj.y, bk.y);
                w = fmaxf(w, 0.f); h = fmaxf(h, 0.f);
                float inter = w * h;
                float iou = inter / (aj + ka - inter);
                if (iou > NMS_T) atomicOr(&s_sup[j >> 5], 1u << (j & 31));
            }
            __syncthreads();
        }
    }
    __syncthreads();

    // ---------- write output ----------
    for (int r = tid; r < TOPK; r += NT) {
        float e0 = 0.f, e1 = 0.f, e2 = 0.f, e3 = 0.f, e4 = 0.f;
        if (r < nkeep) {
            int k = s_keep[r];
            float4 bk = s_box[k];
            e0 = s_val[k]; e1 = bk.x; e2 = bk.y; e3 = bk.z; e4 = bk.w;
        }
        float* row = outp + r * 5;
        row[0] = e0; row[1] = e1; row[2] = e2; row[3] = e3; row[4] = e4;
    }
}

// ---------------------------------------------------------------------------
extern "C" void kernel_launch(void* const* d_in, const int* in_sizes, int n_in,
                              void* d_out, int out_size) {
    const float *loc = nullptr, *conf = nullptr, *prior = nullptr;
    for (int i = 0; i < n_in; ++i) {
        long long sz = in_sizes[i];
        if      (sz == (long long)BATCH * PRIORS * 4)    loc   = (const float*)d_in[i];
        else if (sz == (long long)BATCH * PRIORS * NUMC) conf  = (const float*)d_in[i];
        else if (sz == (long long)PRIORS * 4)            prior = (const float*)d_in[i];
    }
    prep_kernel<<<(BATCH * PRIORS + NT - 1) / NT, NT>>>(loc, conf, prior);
    gather_kernel<<<BATCH * NCLS * SPLIT, NT>>>();
    nms_kernel<<<BATCH * NUMC, NT>>>((float*)d_out);
    (void)out_size;
}

// round 9
// speedup vs baseline: 1.6329x; 1.6329x over previous
#include <cuda_runtime.h>
#include <cstdint>
#include <cstddef>

#define BATCH   32
#define PRIORS  32768
#define NUMC    21
#define NCLS    20
#define NMSK    1000
#define TOPK    200
#define CONF_T  0.01f
#define NMS_T   0.3f
#define NT      256
#define T0F     0.95f
#define CAP     2048
#define BCAP    64

typedef unsigned long long ull;
#define FULL 0xffffffffu

__device__ float4 g_decoded[(size_t)BATCH * PRIORS];
__device__ ull    g_cand[(size_t)BATCH * NCLS * CAP];
__device__ int    g_cnt[BATCH * NCLS];       // zero-init at load; self-zeroed by nms
__device__ int    g_cntlow[BATCH * NCLS];
__device__ int    g_ovf[BATCH * NCLS];

// ---------------------------------------------------------------------------
// Kernel 1: fused decode + candidate gather (one pass over conf, staged in smem)
// ---------------------------------------------------------------------------
__global__ __launch_bounds__(NT) void prep_gather(const float* __restrict__ loc,
                                                  const float* __restrict__ conf,
                                                  const float* __restrict__ prior) {
    __shared__ __align__(16) float s_stage[NT * NUMC];   // 21504 B
    __shared__ ull s_cbuf[NCLS][BCAP];                   // 10240 B
    __shared__ int s_ccnt[NCLS], s_lowc[NCLS];

    const int blk = blockIdx.x, tid = threadIdx.x, lane = tid & 31, wid = tid >> 5;

    // coalesced stage of this block's 256 conf rows
    const float4* src = reinterpret_cast<const float4*>(conf + (size_t)blk * NT * NUMC);
    float4* st = reinterpret_cast<float4*>(s_stage);
    for (int i = tid; i < NT * NUMC / 4; i += NT) st[i] = src[i];
    if (tid < NCLS) { s_ccnt[tid] = 0; s_lowc[tid] = 0; }

    // decode this thread's box
    const int idx = blk * NT + tid;
    const int p   = idx & (PRIORS - 1);
    const int b   = idx >> 15;
    {
        float4 l  = reinterpret_cast<const float4*>(loc)[idx];
        float4 pr = reinterpret_cast<const float4*>(prior)[p];
        float cx = pr.x + (l.x * 0.1f) * pr.z;
        float cy = pr.y + (l.y * 0.1f) * pr.w;
        float w  = pr.z * expf(l.z * 0.2f);
        float h  = pr.w * expf(l.w * 0.2f);
        float x1 = cx - w * 0.5f;
        float y1 = cy - h * 0.5f;
        g_decoded[idx] = make_float4(x1, y1, x1 + w, y1 + h);
    }
    __syncthreads();

    const float* row = s_stage + tid * NUMC;
#pragma unroll
    for (int c = 0; c < NCLS; ++c) {
        float x = row[c + 1];
        bool pass = (x > T0F);
        bool low  = (x > CONF_T) && !pass;
        unsigned int pm = __ballot_sync(FULL, pass);
        unsigned int lm = __ballot_sync(FULL, low);
        if (pm) {
            int leader = __ffs(pm) - 1;
            int n = __popc(pm);
            int base;
            if (lane == leader) base = atomicAdd(&s_ccnt[c], n);   // smem atomic: cheap
            base = __shfl_sync(FULL, base, leader);
            if (pass) {
                int pos = base + __popc(pm & ((1u << lane) - 1u));
                if (pos < BCAP)
                    s_cbuf[c][pos] = ((ull)__float_as_uint(x) << 32)
                                   | (ull)(0xFFFFFFFFu - (unsigned int)p);
            }
        }
        if (lm && lane == __ffs(lm) - 1) atomicAdd(&s_lowc[c], __popc(lm));
    }
    __syncthreads();

    // flush: warp wid handles classes wid, wid+8, wid+16 — ONE global atomic each
    for (int c = wid; c < NCLS; c += 8) {
        int bc = b * NCLS + c;
        int n  = s_ccnt[c];
        int ov = (n > BCAP);
        if (ov) n = BCAP;
        int gbase;
        if (lane == 0) gbase = atomicAdd(&g_cnt[bc], n);
        gbase = __shfl_sync(FULL, gbase, 0);
        if (gbase + n > CAP) ov = 1;
        for (int i = lane; i < n; i += 32) {
            int q = gbase + i;
            if (q < CAP) g_cand[(size_t)bc * CAP + q] = s_cbuf[c][i];
        }
        if (lane == 0) {
            if (ov) atomicExch(&g_ovf[bc], 1);
            int lw = s_lowc[c];
            if (lw) atomicAdd(&g_cntlow[bc], lw);
        }
    }
}

// ---------------------------------------------------------------------------
// Kernel 2: per (batch,class) top-1000 select + single-warp backward NMS
// ---------------------------------------------------------------------------
__global__ __launch_bounds__(NT) void nms_kernel(float* __restrict__ out,
                                                 const float* __restrict__ conf) {
    const int bx = blockIdx.x, b = bx / NUMC, cc = bx % NUMC;
    const int tid = threadIdx.x;
    float* outp = out + (size_t)bx * (TOPK * 5);

    if (cc == 0) {
        for (int i = tid; i < TOPK * 5; i += NT) outp[i] = 0.f;
        return;
    }
    const int bc = b * NCLS + (cc - 1);

    __shared__ __align__(16) unsigned char s_mem[28672];
    ull*    s_keys = reinterpret_cast<ull*>(s_mem);            // [0,16K)
    ull*    s_dst  = reinterpret_cast<ull*>(s_mem + 16384);    // [16K,24K)
    int*    s_hist = reinterpret_cast<int*>(s_mem);            // fallback alias
    float4* s_box  = reinterpret_cast<float4*>(s_mem);         // [0,16K) late
    float*  s_val  = reinterpret_cast<float*>(s_mem + 24576);  // [24K,28K)
    __shared__ int s_shist[256];
    __shared__ float4 s_kbox[TOPK];
    __shared__ float  s_karea[TOPK];
    __shared__ int    s_keep[TOPK];
    __shared__ int s_cnt2, s_pivch, s_pivkk, s_pivbin, s_selb, s_sab, s_pc, s_nk;
    __shared__ unsigned int s_umax;

    const int lane = tid & 31;
    const int wid  = tid >> 5;
    const int nmsw = bx & 7;            // NMS warp spread across SMSPs

    int cnt = g_cnt[bc];
    bool need_fb = g_ovf[bc] || (cnt > CAP) || (cnt < NMSK && g_cntlow[bc] > 0);
    unsigned int Tgt = __float_as_uint(T0F);

    if (tid == 0) s_umax = 0u;
    __syncthreads();

    if (!need_fb) {
        const ull* cand = g_cand + (size_t)bc * CAP;
        unsigned int um = 0u;
        for (int i = tid; i < cnt; i += NT) {
            ull k = __ldg(cand + i);
            s_keys[i] = k;
            unsigned int bits = (unsigned int)(k >> 32);
            um = um > bits ? um : bits;
        }
#pragma unroll
        for (int o = 16; o; o >>= 1) {
            unsigned int t = __shfl_down_sync(FULL, um, o);
            um = um > t ? um : t;
        }
        if (lane == 0) atomicMax(&s_umax, um);
        __syncthreads();
    } else {
        // exact fallback: 12-bit histogram over strided raw conf column (rare)
        const float* base = conf + ((size_t)b << 15) * NUMC + cc;
        for (int i = tid; i < 4096; i += NT) s_hist[i] = 0;
        if (tid == 0) s_pivch = -1;
        __syncthreads();
        for (int i = tid; i < PRIORS; i += NT) {
            float x = __ldg(base + (size_t)i * NUMC);
            unsigned int bits = (x > CONF_T) ? __float_as_uint(x) : 0u;
            atomicAdd(&s_hist[bits >> 20], 1);
        }
        __syncthreads();
        { int cs = 0; for (int j = 0; j < 16; ++j) cs += s_hist[tid * 16 + j]; s_shist[tid] = cs; }
        __syncthreads();
        for (int d = 1; d < 256; d <<= 1) {
            int v = (tid + d < 256) ? s_shist[tid + d] : 0;
            __syncthreads();
            s_shist[tid] += v;
            __syncthreads();
        }
        { int suf = s_shist[tid]; int sufn = (tid < 255) ? s_shist[tid + 1] : 0;
          if (suf >= NMSK && sufn < NMSK) { s_pivch = tid; s_pivkk = NMSK - sufn; } }
        __syncthreads();
        if (tid == 0) {
            int pb = 1;
            if (s_pivch >= 0) {
                int ch = s_pivch, kk = s_pivkk, run = 0;
                for (int j = 15; j >= 0; --j) {
                    run += s_hist[ch * 16 + j];
                    if (run >= kk) { pb = ch * 16 + j; break; }
                }
            }
            if (pb < 1) pb = 1;
            s_pivbin = pb; s_cnt2 = 0; s_umax = 0u;
        }
        __syncthreads();
        Tgt = (((unsigned int)s_pivbin) << 20) - 1u;
        unsigned int um = 0u;
        for (int i = tid; i < PRIORS; i += NT) {
            float x = __ldg(base + (size_t)i * NUMC);
            unsigned int bits = __float_as_uint(x);
            if (x > CONF_T && bits > Tgt) {
                int pos = atomicAdd(&s_cnt2, 1);
                if (pos < CAP)
                    s_keys[pos] = ((ull)bits << 32) | (ull)(0xFFFFFFFFu - (unsigned int)i);
                um = um > bits ? um : bits;
            }
        }
#pragma unroll
        for (int o = 16; o; o >>= 1) {
            unsigned int t = __shfl_down_sync(FULL, um, o);
            um = um > t ? um : t;
        }
        if (lane == 0) atomicMax(&s_umax, um);
        __syncthreads();
        cnt = s_cnt2; if (cnt > CAP - 1) cnt = CAP - 1;
    }

    // ---------- refine to <=1024 ----------
    bool sorted2048 = false;
    int sabove = cnt;
    if (cnt > 1024) {
        unsigned int base = Tgt;
        unsigned int span = s_umax - base;
        int nbits = 32 - __clz((int)span);
        int shift = nbits > 8 ? nbits - 8 : 0;
        s_shist[tid] = 0;
        if (tid == 0) s_selb = -1;
        __syncthreads();
        for (int i = tid; i < cnt; i += NT) {
            unsigned int bits = (unsigned int)(s_keys[i] >> 32);
            atomicAdd(&s_shist[(bits - base) >> shift], 1);
        }
        __syncthreads();
        if (wid == 0) {
            int base8 = lane * 8;
            int h[8]; int s = 0;
#pragma unroll
            for (int j = 0; j < 8; ++j) { h[j] = s_shist[base8 + j]; s += h[j]; }
            int suf = s;
#pragma unroll
            for (int o = 1; o < 32; o <<= 1) {
                int t = __shfl_down_sync(FULL, suf, o);
                if (lane + o < 32) suf += t;
            }
            int sufn = __shfl_down_sync(FULL, suf, 1);
            if (lane == 31) sufn = 0;
            if (suf >= NMSK && sufn < NMSK) {
                int run = 0;
#pragma unroll
                for (int j = 7; j >= 0; --j) {
                    run += h[j];
                    if (sufn + run >= NMSK) { s_selb = base8 + j; s_sab = sufn + run; break; }
                }
            }
        }
        __syncthreads();
        int selb = s_selb;
        if (selb >= 0 && s_sab <= 1024) {
            unsigned int T2 = base + (((unsigned int)selb) << shift);
            if (tid == 0) s_pc = 0;
            for (int i = tid; i < 1024; i += NT) s_dst[i] = 0ull;
            __syncthreads();
            for (int i = tid; i < cnt; i += NT) {
                ull k = s_keys[i];
                if ((unsigned int)(k >> 32) >= T2) {
                    int p = atomicAdd(&s_pc, 1);
                    if (p < 1024) s_dst[p] = k;
                }
            }
            sabove = s_sab;
        } else {
            for (int i = cnt + tid; i < 2048; i += NT) s_keys[i] = 0ull;
            for (int k2 = 2; k2 <= 2048; k2 <<= 1) {
                for (int j = k2 >> 1; j > 0; j >>= 1) {
                    if (j >= 16) __syncthreads(); else __syncwarp();
                    for (int i = tid; i < 2048; i += NT) {
                        int l = i ^ j;
                        if (l > i) {
                            ull a = s_keys[i], bb = s_keys[l];
                            bool up = ((i & k2) == 0);
                            if (up ? (a < bb) : (a > bb)) { s_keys[i] = bb; s_keys[l] = a; }
                        }
                    }
                }
            }
            __syncthreads();
            for (int i = tid; i < 1024; i += NT) s_dst[i] = (i < NMSK) ? s_keys[i] : 0ull;
            sorted2048 = true;
        }
    } else {
        for (int i = tid; i < 1024; i += NT) s_dst[i] = (i < cnt) ? s_keys[i] : 0ull;
    }
    __syncthreads();
    if (!sorted2048) {
        for (int k2 = 2; k2 <= 1024; k2 <<= 1) {
            for (int j = k2 >> 1; j > 0; j >>= 1) {
                if (j >= 16) __syncthreads(); else __syncwarp();
                for (int i = tid; i < 1024; i += NT) {
                    int l = i ^ j;
                    if (l > i) {
                        ull a = s_dst[i], bb = s_dst[l];
                        bool up = ((i & k2) == 0);
                        if (up ? (a < bb) : (a > bb)) { s_dst[i] = bb; s_dst[l] = a; }
                    }
                }
            }
        }
        __syncthreads();
    }

    // ---------- extract boxes (s_box aliases dead s_keys) ----------
    const float4* dec = g_decoded + ((size_t)b << 15);
    const int nvalid = sabove < NMSK ? sabove : NMSK;
    for (int r = tid; r < 1024; r += NT) {
        float v = 0.f;
        float4 bb = make_float4(0.f, 0.f, 0.f, 0.f);
        if (r < NMSK) {
            ull key = s_dst[r];
            unsigned int bits = (unsigned int)(key >> 32);
            v = __uint_as_float(bits);
            if (v > CONF_T) {
                unsigned int p = 0xFFFFFFFFu - (unsigned int)(key & 0xFFFFFFFFull);
                bb = __ldg(dec + p);
            } else v = 0.f;
        }
        s_box[r] = bb;
        s_val[r] = v;
    }
    __syncthreads();

    // ---------- single-warp backward greedy NMS (warp nmsw, no block barriers) ----------
    if (wid == nmsw) {
        int nk = 0;
        for (int k = 0; k < nvalid; ++k) {
            float vk = s_val[k];
            if (vk <= CONF_T) break;
            float4 bk = s_box[k];
            float ka = (bk.z - bk.x) * (bk.w - bk.y);
            bool sup = false;
            for (int j = lane; j < nk; j += 32) {
                float4 ba = s_kbox[j];
                float w = fminf(bk.z, ba.z) - fmaxf(bk.x, ba.x);
                float h = fminf(bk.w, ba.w) - fmaxf(bk.y, ba.y);
                w = fmaxf(w, 0.f); h = fmaxf(h, 0.f);
                float inter = w * h;
                if (inter / (ka + s_karea[j] - inter) > NMS_T) { sup = true; break; }
            }
            if (!__any_sync(FULL, sup)) {
                if (lane == 0) { s_kbox[nk] = bk; s_karea[nk] = ka; s_keep[nk] = k; }
                __syncwarp();
                if (++nk >= TOPK) break;
            }
        }
        if (lane == 0) s_nk = nk;
    }
    __syncthreads();

    // ---------- write output + self-zero counters ----------
    int nkeep = s_nk;
    for (int r = tid; r < TOPK; r += NT) {
        float e0 = 0.f, e1 = 0.f, e2 = 0.f, e3 = 0.f, e4 = 0.f;
        if (r < nkeep) {
            int k = s_keep[r];
            float4 bk = s_box[k];
            e0 = s_val[k]; e1 = bk.x; e2 = bk.y; e3 = bk.z; e4 = bk.w;
        }
        float* row = outp + r * 5;
        row[0] = e0; row[1] = e1; row[2] = e2; row[3] = e3; row[4] = e4;
    }
    if (tid == 0) { g_cnt[bc] = 0; g_cntlow[bc] = 0; g_ovf[bc] = 0; }
}

// ---------------------------------------------------------------------------
extern "C" void kernel_launch(void* const* d_in, const int* in_sizes, int n_in,
                              void* d_out, int out_size) {
    const float *loc = nullptr, *conf = nullptr, *prior = nullptr;
    for (int i = 0; i < n_in; ++i) {
        long long sz = in_sizes[i];
        if      (sz == (long long)BATCH * PRIORS * 4)    loc   = (const float*)d_in[i];
        else if (sz == (long long)BATCH * PRIORS * NUMC) conf  = (const float*)d_in[i];
        else if (sz == (long long)PRIORS * 4)            prior = (const float*)d_in[i];
    }
    prep_gather<<<BATCH * PRIORS / NT, NT>>>(loc, conf, prior);
    nms_kernel<<<BATCH * NUMC, NT>>>((float*)d_out, conf);
    (void)out_size;
}